// round 3
// baseline (speedup 1.0000x reference)
#include <cuda_runtime.h>

#define N_NODES 50000
#define N_EDGES 800000
#define IN_CH 512
#define HID 256

// Scratch: __device__ globals, referenced DIRECTLY in device code.
__device__ float g_G[(size_t)N_NODES * HID];    // GEMM output per layer
__device__ float g_AGG[(size_t)N_NODES * HID];  // aggregated output per layer
__device__ float g_dinv[N_NODES];               // deg -> dinv in place

// ---------------- degree / norm ----------------
__global__ void k_deg_init() {
    int i = blockIdx.x * blockDim.x + threadIdx.x;
    if (i < N_NODES) g_dinv[i] = 1.0f;  // self-loop
}
__global__ void k_deg_accum(const int* __restrict__ ei) {
    int i = blockIdx.x * blockDim.x + threadIdx.x;
    if (i < N_EDGES) {
        int d = ei[N_EDGES + i];  // dst row
        if ((unsigned)d < N_NODES) atomicAdd(&g_dinv[d], 1.0f);
    }
}
__global__ void k_dinv() {
    int i = blockIdx.x * blockDim.x + threadIdx.x;
    if (i < N_NODES) g_dinv[i] = rsqrtf(g_dinv[i]);  // deg >= 1 always
}

// ---------------- SGEMM 128x128x8, fp32, writes g_G ----------------
// FIRST: A = x param (K=IN_CH). else: A = relu(g_AGG) (K=HID).
template <bool FIRST>
__global__ __launch_bounds__(256) void k_sgemm(
    const float* __restrict__ Ax, const float* __restrict__ B)
{
    constexpr int BM = 128, BK = 8;
    constexpr int N = HID;
    constexpr int K = FIRST ? IN_CH : HID;
    const float* A = FIRST ? Ax : (const float*)g_AGG;

    __shared__ float As[BK][BM];
    __shared__ float Bs[BK][128];

    const int tid = threadIdx.x;
    const int bm = blockIdx.y * BM;
    const int bn = blockIdx.x * 128;

    const int aRow = tid >> 1;
    const int aCol = (tid & 1) * 4;
    const int bRow = tid >> 5;
    const int bCol = (tid & 31) * 4;

    const int tRow = (tid / 16) * 8;
    const int tCol = (tid % 16) * 8;

    float acc[8][8];
#pragma unroll
    for (int i = 0; i < 8; i++)
#pragma unroll
        for (int j = 0; j < 8; j++) acc[i][j] = 0.0f;

    for (int k0 = 0; k0 < K; k0 += BK) {
        float4 av = make_float4(0.f, 0.f, 0.f, 0.f);
        int gm = bm + aRow;
        if (gm < N_NODES) av = *(const float4*)(A + (size_t)gm * K + k0 + aCol);
        if (!FIRST) {
            av.x = fmaxf(av.x, 0.f); av.y = fmaxf(av.y, 0.f);
            av.z = fmaxf(av.z, 0.f); av.w = fmaxf(av.w, 0.f);
        }
        As[aCol + 0][aRow] = av.x;
        As[aCol + 1][aRow] = av.y;
        As[aCol + 2][aRow] = av.z;
        As[aCol + 3][aRow] = av.w;
        float4 bv = *(const float4*)(B + (size_t)(k0 + bRow) * N + bn + bCol);
        *(float4*)&Bs[bRow][bCol] = bv;
        __syncthreads();

#pragma unroll
        for (int k = 0; k < BK; k++) {
            float a[8], b[8];
            *(float4*)&a[0] = *(const float4*)&As[k][tRow];
            *(float4*)&a[4] = *(const float4*)&As[k][tRow + 4];
            *(float4*)&b[0] = *(const float4*)&Bs[k][tCol];
            *(float4*)&b[4] = *(const float4*)&Bs[k][tCol + 4];
#pragma unroll
            for (int i = 0; i < 8; i++)
#pragma unroll
                for (int j = 0; j < 8; j++)
                    acc[i][j] += a[i] * b[j];
        }
        __syncthreads();
    }

#pragma unroll
    for (int i = 0; i < 8; i++) {
        int gm = bm + tRow + i;
        if (gm < N_NODES) {
            *(float4*)(g_G + (size_t)gm * N + bn + tCol) =
                make_float4(acc[i][0], acc[i][1], acc[i][2], acc[i][3]);
            *(float4*)(g_G + (size_t)gm * N + bn + tCol + 4) =
                make_float4(acc[i][4], acc[i][5], acc[i][6], acc[i][7]);
        }
    }
}

// ---------------- AGG init: b + dinv^2 * G (self-loop term) ----------------
__global__ void k_agg_init(const float* __restrict__ bias) {
    int idx = blockIdx.x * blockDim.x + threadIdx.x;  // one float4
    if (idx >= N_NODES * (HID / 4)) return;
    int node = idx / (HID / 4);
    int c4 = idx % (HID / 4);
    float di = g_dinv[node];
    float w = di * di;
    float4 g = ((const float4*)g_G)[idx];
    float4 bv = ((const float4*)bias)[c4];
    float4 r;
    r.x = bv.x + w * g.x;
    r.y = bv.y + w * g.y;
    r.z = bv.z + w * g.z;
    r.w = bv.w + w * g.w;
    ((float4*)g_AGG)[idx] = r;
}

// ---------------- edge scatter: one warp per edge ----------------
__global__ void k_scatter(const int* __restrict__ ei) {
    int t = blockIdx.x * blockDim.x + threadIdx.x;
    int e = t >> 5;
    int lane = t & 31;
    if (e >= N_EDGES) return;
    int s = ei[e];            // src
    int d = ei[N_EDGES + e];  // dst
    if ((unsigned)s >= N_NODES || (unsigned)d >= N_NODES) return;  // safety
    float w = g_dinv[s] * g_dinv[d];
    const float4* gs = (const float4*)(g_G + (size_t)s * HID);
    float* out = g_AGG + (size_t)d * HID;
#pragma unroll
    for (int j = 0; j < 2; j++) {
        int c4 = lane + 32 * j;
        float4 v = gs[c4];
        int c = c4 * 4;
        atomicAdd(out + c + 0, w * v.x);
        atomicAdd(out + c + 1, w * v.y);
        atomicAdd(out + c + 2, w * v.z);
        atomicAdd(out + c + 3, w * v.w);
    }
}

// ---------------- readout: warp per node ----------------
__global__ void k_readout(const float* __restrict__ Wout,
                          const float* __restrict__ bout, float* __restrict__ out) {
    int t = blockIdx.x * blockDim.x + threadIdx.x;
    int node = t >> 5;
    int lane = t & 31;
    if (node >= N_NODES) return;
    const float* row = g_AGG + (size_t)node * HID;
    float acc = 0.0f;
#pragma unroll
    for (int j = lane; j < HID; j += 32)
        acc += fmaxf(row[j], 0.0f) * Wout[j];
#pragma unroll
    for (int o = 16; o; o >>= 1) acc += __shfl_xor_sync(0xffffffffu, acc, o);
    if (lane == 0) out[node] = acc + bout[0];
}

extern "C" void kernel_launch(void* const* d_in, const int* in_sizes, int n_in,
                              void* d_out, int out_size) {
    const float* x = (const float*)d_in[0];
    const int* ei = (const int*)d_in[1];  // edge_index: int32 (JAX x64 disabled)
    const float* W0 = (const float*)d_in[2];
    const float* b0 = (const float*)d_in[3];
    const float* W1 = (const float*)d_in[4];
    const float* b1 = (const float*)d_in[5];
    const float* W2 = (const float*)d_in[6];
    const float* b2 = (const float*)d_in[7];
    const float* Wout = (const float*)d_in[8];
    const float* bout = (const float*)d_in[9];
    float* out = (float*)d_out;

    // degree + normalization
    k_deg_init<<<(N_NODES + 255) / 256, 256>>>();
    k_deg_accum<<<(N_EDGES + 255) / 256, 256>>>(ei);
    k_dinv<<<(N_NODES + 255) / 256, 256>>>();

    dim3 gemmGrid(HID / 128, (N_NODES + 127) / 128);
    const int aggInitBlocks = (N_NODES * (HID / 4) + 255) / 256;
    const int scatterBlocks = (N_EDGES * 32 + 255) / 256;

    // layer 0
    k_sgemm<true><<<gemmGrid, 256>>>(x, W0);
    k_agg_init<<<aggInitBlocks, 256>>>(b0);
    k_scatter<<<scatterBlocks, 256>>>(ei);

    // layer 1
    k_sgemm<false><<<gemmGrid, 256>>>(nullptr, W1);
    k_agg_init<<<aggInitBlocks, 256>>>(b1);
    k_scatter<<<scatterBlocks, 256>>>(ei);

    // layer 2
    k_sgemm<false><<<gemmGrid, 256>>>(nullptr, W2);
    k_agg_init<<<aggInitBlocks, 256>>>(b2);
    k_scatter<<<scatterBlocks, 256>>>(ei);

    // readout
    k_readout<<<(N_NODES * 32 + 255) / 256, 256>>>(Wout, bout, out);
}

// round 4
// speedup vs baseline: 2.1677x; 2.1677x over previous
#include <cuda_runtime.h>

#define N_NODES 50000
#define N_EDGES 800000
#define IN_CH 512
#define HID 256

// Scratch: __device__ globals, referenced DIRECTLY in device code.
__device__ float g_G[(size_t)N_NODES * HID];    // GEMM output per layer
__device__ float g_AGG[(size_t)N_NODES * HID];  // aggregated output per layer
__device__ float g_dinv[N_NODES];
__device__ int   g_degi[N_NODES];               // in-degree counts (excl self)
__device__ int   g_rowstart[N_NODES + 1];       // CSR row offsets (by dst)
__device__ int   g_cursor[N_NODES];             // fill cursors
__device__ int   g_esrc[N_EDGES];               // CSR: src node per slot
__device__ float g_ew[N_EDGES];                 // CSR: edge weight per slot

// ---------------- CSR build ----------------
__global__ void k_zero_deg() {
    int i = blockIdx.x * blockDim.x + threadIdx.x;
    if (i < N_NODES) g_degi[i] = 0;
}
__global__ void k_deg_accum(const int* __restrict__ ei) {
    int i = blockIdx.x * blockDim.x + threadIdx.x;
    if (i < N_EDGES) {
        int d = ei[N_EDGES + i];
        if ((unsigned)d < N_NODES) atomicAdd(&g_degi[d], 1);
    }
}
__global__ void k_dinv() {
    int i = blockIdx.x * blockDim.x + threadIdx.x;
    if (i < N_NODES) g_dinv[i] = rsqrtf(1.0f + (float)g_degi[i]);  // +1 self-loop
}
// single-block exclusive scan of g_degi -> g_rowstart (+ cursor copy)
__global__ __launch_bounds__(1024) void k_scan() {
    __shared__ int sums[1024];
    const int t = threadIdx.x;
    const int CHUNK = (N_NODES + 1023) / 1024;  // 49
    int beg = t * CHUNK;
    int end = beg + CHUNK; if (end > N_NODES) end = N_NODES;
    int s = 0;
    for (int i = beg; i < end; i++) s += g_degi[i];
    sums[t] = s;
    __syncthreads();
    for (int o = 1; o < 1024; o <<= 1) {
        int v = (t >= o) ? sums[t - o] : 0;
        __syncthreads();
        sums[t] += v;
        __syncthreads();
    }
    int run = (t == 0) ? 0 : sums[t - 1];
    for (int i = beg; i < end; i++) {
        g_rowstart[i] = run;
        g_cursor[i] = run;
        run += g_degi[i];
    }
    if (t == 1023) g_rowstart[N_NODES] = run;
}
__global__ void k_fill(const int* __restrict__ ei) {
    int e = blockIdx.x * blockDim.x + threadIdx.x;
    if (e >= N_EDGES) return;
    int s = ei[e];
    int d = ei[N_EDGES + e];
    if ((unsigned)s >= N_NODES || (unsigned)d >= N_NODES) return;
    int pos = atomicAdd(&g_cursor[d], 1);
    g_esrc[pos] = s;
    g_ew[pos] = g_dinv[s] * g_dinv[d];
}

// ---------------- SGEMM 128x128x8, fp32, writes g_G ----------------
template <bool FIRST>
__global__ __launch_bounds__(256) void k_sgemm(
    const float* __restrict__ Ax, const float* __restrict__ B)
{
    constexpr int BM = 128, BK = 8;
    constexpr int N = HID;
    constexpr int K = FIRST ? IN_CH : HID;
    const float* A = FIRST ? Ax : (const float*)g_AGG;

    __shared__ float As[BK][BM];
    __shared__ float Bs[BK][128];

    const int tid = threadIdx.x;
    const int bm = blockIdx.y * BM;
    const int bn = blockIdx.x * 128;

    const int aRow = tid >> 1;
    const int aCol = (tid & 1) * 4;
    const int bRow = tid >> 5;
    const int bCol = (tid & 31) * 4;

    const int tRow = (tid / 16) * 8;
    const int tCol = (tid % 16) * 8;

    float acc[8][8];
#pragma unroll
    for (int i = 0; i < 8; i++)
#pragma unroll
        for (int j = 0; j < 8; j++) acc[i][j] = 0.0f;

    for (int k0 = 0; k0 < K; k0 += BK) {
        float4 av = make_float4(0.f, 0.f, 0.f, 0.f);
        int gm = bm + aRow;
        if (gm < N_NODES) av = *(const float4*)(A + (size_t)gm * K + k0 + aCol);
        if (!FIRST) {
            av.x = fmaxf(av.x, 0.f); av.y = fmaxf(av.y, 0.f);
            av.z = fmaxf(av.z, 0.f); av.w = fmaxf(av.w, 0.f);
        }
        As[aCol + 0][aRow] = av.x;
        As[aCol + 1][aRow] = av.y;
        As[aCol + 2][aRow] = av.z;
        As[aCol + 3][aRow] = av.w;
        float4 bv = *(const float4*)(B + (size_t)(k0 + bRow) * N + bn + bCol);
        *(float4*)&Bs[bRow][bCol] = bv;
        __syncthreads();

#pragma unroll
        for (int k = 0; k < BK; k++) {
            float a[8], b[8];
            *(float4*)&a[0] = *(const float4*)&As[k][tRow];
            *(float4*)&a[4] = *(const float4*)&As[k][tRow + 4];
            *(float4*)&b[0] = *(const float4*)&Bs[k][tCol];
            *(float4*)&b[4] = *(const float4*)&Bs[k][tCol + 4];
#pragma unroll
            for (int i = 0; i < 8; i++)
#pragma unroll
                for (int j = 0; j < 8; j++)
                    acc[i][j] += a[i] * b[j];
        }
        __syncthreads();
    }

#pragma unroll
    for (int i = 0; i < 8; i++) {
        int gm = bm + tRow + i;
        if (gm < N_NODES) {
            *(float4*)(g_G + (size_t)gm * N + bn + tCol) =
                make_float4(acc[i][0], acc[i][1], acc[i][2], acc[i][3]);
            *(float4*)(g_G + (size_t)gm * N + bn + tCol + 4) =
                make_float4(acc[i][4], acc[i][5], acc[i][6], acc[i][7]);
        }
    }
}

// ---------------- CSR gather aggregation: one warp per node ----------------
// AGG[n] = b + dinv[n]^2 * G[n] + sum_{e in row(n)} w_e * G[src_e]
__global__ __launch_bounds__(256) void k_gather(const float* __restrict__ bias) {
    int t = blockIdx.x * blockDim.x + threadIdx.x;
    int node = t >> 5;
    int lane = t & 31;
    if (node >= N_NODES) return;

    int beg = g_rowstart[node];
    int end = g_rowstart[node + 1];
    float di = g_dinv[node];
    float wself = di * di;

    const float4* grow = (const float4*)(g_G + (size_t)node * HID);
    const float4* b4 = (const float4*)bias;

    float4 acc0 = b4[lane];
    float4 acc1 = b4[lane + 32];
    float4 v0 = grow[lane];
    float4 v1 = grow[lane + 32];
    acc0.x += wself * v0.x; acc0.y += wself * v0.y;
    acc0.z += wself * v0.z; acc0.w += wself * v0.w;
    acc1.x += wself * v1.x; acc1.y += wself * v1.y;
    acc1.z += wself * v1.z; acc1.w += wself * v1.w;

    for (int e = beg; e < end; e++) {
        int s = g_esrc[e];
        float w = g_ew[e];
        const float4* gs = (const float4*)(g_G + (size_t)s * HID);
        float4 u0 = gs[lane];
        float4 u1 = gs[lane + 32];
        acc0.x += w * u0.x; acc0.y += w * u0.y;
        acc0.z += w * u0.z; acc0.w += w * u0.w;
        acc1.x += w * u1.x; acc1.y += w * u1.y;
        acc1.z += w * u1.z; acc1.w += w * u1.w;
    }

    float4* arow = (float4*)(g_AGG + (size_t)node * HID);
    arow[lane] = acc0;
    arow[lane + 32] = acc1;
}

// ---------------- readout: warp per node ----------------
__global__ void k_readout(const float* __restrict__ Wout,
                          const float* __restrict__ bout, float* __restrict__ out) {
    int t = blockIdx.x * blockDim.x + threadIdx.x;
    int node = t >> 5;
    int lane = t & 31;
    if (node >= N_NODES) return;
    const float* row = g_AGG + (size_t)node * HID;
    float acc = 0.0f;
#pragma unroll
    for (int j = lane; j < HID; j += 32)
        acc += fmaxf(row[j], 0.0f) * Wout[j];
#pragma unroll
    for (int o = 16; o; o >>= 1) acc += __shfl_xor_sync(0xffffffffu, acc, o);
    if (lane == 0) out[node] = acc + bout[0];
}

extern "C" void kernel_launch(void* const* d_in, const int* in_sizes, int n_in,
                              void* d_out, int out_size) {
    const float* x = (const float*)d_in[0];
    const int* ei = (const int*)d_in[1];  // int32 (JAX x64 disabled)
    const float* W0 = (const float*)d_in[2];
    const float* b0 = (const float*)d_in[3];
    const float* W1 = (const float*)d_in[4];
    const float* b1 = (const float*)d_in[5];
    const float* W2 = (const float*)d_in[6];
    const float* b2 = (const float*)d_in[7];
    const float* Wout = (const float*)d_in[8];
    const float* bout = (const float*)d_in[9];
    float* out = (float*)d_out;

    // CSR build (by dst) + normalization
    k_zero_deg<<<(N_NODES + 255) / 256, 256>>>();
    k_deg_accum<<<(N_EDGES + 255) / 256, 256>>>(ei);
    k_dinv<<<(N_NODES + 255) / 256, 256>>>();
    k_scan<<<1, 1024>>>();
    k_fill<<<(N_EDGES + 255) / 256, 256>>>(ei);

    dim3 gemmGrid(HID / 128, (N_NODES + 127) / 128);
    const int gatherBlocks = (N_NODES * 32 + 255) / 256;

    // layer 0
    k_sgemm<true><<<gemmGrid, 256>>>(x, W0);
    k_gather<<<gatherBlocks, 256>>>(b0);
    // layer 1
    k_sgemm<false><<<gemmGrid, 256>>>(nullptr, W1);
    k_gather<<<gatherBlocks, 256>>>(b1);
    // layer 2
    k_sgemm<false><<<gemmGrid, 256>>>(nullptr, W2);
    k_gather<<<gatherBlocks, 256>>>(b2);
    // readout
    k_readout<<<(N_NODES * 32 + 255) / 256, 256>>>(Wout, bout, out);
}

// round 5
// speedup vs baseline: 2.4762x; 1.1423x over previous
#include <cuda_runtime.h>

#define N_NODES 50000
#define N_EDGES 800000
#define IN_CH 512
#define HID 256
#define SCAN_BLOCKS ((N_NODES + 255) / 256)  // 196

// Scratch: __device__ globals, referenced DIRECTLY in device code.
__device__ float g_G[(size_t)N_NODES * HID];    // GEMM output per layer
__device__ float g_AGG[(size_t)N_NODES * HID];  // aggregated output per layer
__device__ float g_dinv[N_NODES];
__device__ int   g_degi[N_NODES];               // in-degree counts (excl self)
__device__ int   g_rowstart[N_NODES + 1];       // CSR row offsets (by dst)
__device__ int   g_cursor[N_NODES];             // fill cursors
__device__ int   g_esrc[N_EDGES];               // CSR: src node per slot
__device__ float g_ew[N_EDGES];                 // CSR: edge weight per slot
__device__ int   g_part[SCAN_BLOCKS];           // scan partials

// ---------------- CSR build ----------------
__global__ void k_zero_deg() {
    int i = blockIdx.x * blockDim.x + threadIdx.x;
    if (i < N_NODES) g_degi[i] = 0;
}
__global__ void k_deg_accum(const int* __restrict__ ei) {
    int i = blockIdx.x * blockDim.x + threadIdx.x;
    if (i < N_EDGES) {
        int d = ei[N_EDGES + i];
        if ((unsigned)d < N_NODES) atomicAdd(&g_degi[d], 1);
    }
}
__global__ void k_dinv() {
    int i = blockIdx.x * blockDim.x + threadIdx.x;
    if (i < N_NODES) g_dinv[i] = rsqrtf(1.0f + (float)g_degi[i]);  // +1 self-loop
}
// hierarchical exclusive scan of g_degi -> g_rowstart (+ cursor copy)
__global__ void k_scan1() {  // per-block sums
    __shared__ int sh[256];
    int i = blockIdx.x * 256 + threadIdx.x;
    sh[threadIdx.x] = (i < N_NODES) ? g_degi[i] : 0;
    __syncthreads();
    for (int o = 128; o; o >>= 1) {
        if (threadIdx.x < o) sh[threadIdx.x] += sh[threadIdx.x + o];
        __syncthreads();
    }
    if (threadIdx.x == 0) g_part[blockIdx.x] = sh[0];
}
__global__ void k_scan2() {  // exclusive scan of partials (1 block)
    __shared__ int sh[256];
    int t = threadIdx.x;
    sh[t] = (t < SCAN_BLOCKS) ? g_part[t] : 0;
    __syncthreads();
    for (int o = 1; o < 256; o <<= 1) {
        int v = (t >= o) ? sh[t - o] : 0;
        __syncthreads();
        sh[t] += v;
        __syncthreads();
    }
    if (t < SCAN_BLOCKS) g_part[t] = (t == 0) ? 0 : sh[t - 1];
}
__global__ void k_scan3() {  // per-block exclusive scan + base offset
    __shared__ int sh[256];
    int t = threadIdx.x;
    int i = blockIdx.x * 256 + t;
    int v = (i < N_NODES) ? g_degi[i] : 0;
    sh[t] = v;
    __syncthreads();
    for (int o = 1; o < 256; o <<= 1) {
        int u = (t >= o) ? sh[t - o] : 0;
        __syncthreads();
        sh[t] += u;
        __syncthreads();
    }
    int incl = sh[t];
    int base = g_part[blockIdx.x];
    if (i < N_NODES) {
        int rs = base + incl - v;
        g_rowstart[i] = rs;
        g_cursor[i] = rs;
        if (i == N_NODES - 1) g_rowstart[N_NODES] = base + incl;
    }
}
__global__ void k_fill(const int* __restrict__ ei) {
    int e = blockIdx.x * blockDim.x + threadIdx.x;
    if (e >= N_EDGES) return;
    int s = ei[e];
    int d = ei[N_EDGES + e];
    if ((unsigned)s >= N_NODES || (unsigned)d >= N_NODES) return;
    int pos = atomicAdd(&g_cursor[d], 1);
    g_esrc[pos] = s;
    g_ew[pos] = g_dinv[s] * g_dinv[d];
}

// ---------------- SGEMM 128x128x16, fp32, double-buffered, writes g_G ------
// FIRST: A = x param (K=IN_CH). else: A = relu(g_AGG) (K=HID).
template <bool FIRST>
__global__ __launch_bounds__(256) void k_sgemm(
    const float* __restrict__ Ax, const float* __restrict__ B)
{
    constexpr int BM = 128, BN = 128, BK = 16;
    constexpr int N = HID;
    constexpr int K = FIRST ? IN_CH : HID;
    constexpr int NT = K / BK;
    const float* A = FIRST ? Ax : (const float*)g_AGG;

    __shared__ float As[2][BK][BM];
    __shared__ float Bs[2][BK][BN];

    const int tid = threadIdx.x;
    const int bm = blockIdx.y * BM;
    const int bn = blockIdx.x * BN;

    // A tile: 128x16 = 512 float4 slots; thread handles slot tid and tid+256
    const int aRow0 = tid >> 2;            // 0..63
    const int aCol0 = (tid & 3) * 4;
    const int aRow1 = aRow0 + 64;
    // B tile: 16x128 = 512 float4 slots
    const int bRow0 = tid >> 5;            // 0..7
    const int bCol0 = (tid & 31) * 4;
    const int bRow1 = bRow0 + 8;

    const int tRow = (tid / 16) * 8;
    const int tCol = (tid % 16) * 8;

    const int gmA0 = bm + aRow0;
    const int gmA1 = bm + aRow1;

    float acc[8][8];
#pragma unroll
    for (int i = 0; i < 8; i++)
#pragma unroll
        for (int j = 0; j < 8; j++) acc[i][j] = 0.0f;

    auto loadA = [&](int k0, float4& a0, float4& a1) {
        a0 = make_float4(0.f, 0.f, 0.f, 0.f);
        a1 = make_float4(0.f, 0.f, 0.f, 0.f);
        if (gmA0 < N_NODES) a0 = *(const float4*)(A + (size_t)gmA0 * K + k0 + aCol0);
        if (gmA1 < N_NODES) a1 = *(const float4*)(A + (size_t)gmA1 * K + k0 + aCol0);
        if (!FIRST) {
            a0.x = fmaxf(a0.x, 0.f); a0.y = fmaxf(a0.y, 0.f);
            a0.z = fmaxf(a0.z, 0.f); a0.w = fmaxf(a0.w, 0.f);
            a1.x = fmaxf(a1.x, 0.f); a1.y = fmaxf(a1.y, 0.f);
            a1.z = fmaxf(a1.z, 0.f); a1.w = fmaxf(a1.w, 0.f);
        }
    };
    auto loadB = [&](int k0, float4& v0, float4& v1) {
        v0 = *(const float4*)(B + (size_t)(k0 + bRow0) * N + bn + bCol0);
        v1 = *(const float4*)(B + (size_t)(k0 + bRow1) * N + bn + bCol0);
    };
    auto stage = [&](int buf, const float4& a0, const float4& a1,
                     const float4& v0, const float4& v1) {
        As[buf][aCol0 + 0][aRow0] = a0.x;
        As[buf][aCol0 + 1][aRow0] = a0.y;
        As[buf][aCol0 + 2][aRow0] = a0.z;
        As[buf][aCol0 + 3][aRow0] = a0.w;
        As[buf][aCol0 + 0][aRow1] = a1.x;
        As[buf][aCol0 + 1][aRow1] = a1.y;
        As[buf][aCol0 + 2][aRow1] = a1.z;
        As[buf][aCol0 + 3][aRow1] = a1.w;
        *(float4*)&Bs[buf][bRow0][bCol0] = v0;
        *(float4*)&Bs[buf][bRow1][bCol0] = v1;
    };

    {
        float4 a0, a1, v0, v1;
        loadA(0, a0, a1);
        loadB(0, v0, v1);
        stage(0, a0, a1, v0, v1);
    }
    __syncthreads();

    int buf = 0;
    for (int t = 0; t < NT; t++) {
        float4 a0, a1, v0, v1;
        if (t + 1 < NT) {
            loadA((t + 1) * BK, a0, a1);
            loadB((t + 1) * BK, v0, v1);
        }
#pragma unroll
        for (int k = 0; k < BK; k++) {
            float a[8], b[8];
            *(float4*)&a[0] = *(const float4*)&As[buf][k][tRow];
            *(float4*)&a[4] = *(const float4*)&As[buf][k][tRow + 4];
            *(float4*)&b[0] = *(const float4*)&Bs[buf][k][tCol];
            *(float4*)&b[4] = *(const float4*)&Bs[buf][k][tCol + 4];
#pragma unroll
            for (int i = 0; i < 8; i++)
#pragma unroll
                for (int j = 0; j < 8; j++)
                    acc[i][j] += a[i] * b[j];
        }
        if (t + 1 < NT) {
            stage(buf ^ 1, a0, a1, v0, v1);
            __syncthreads();
            buf ^= 1;
        }
    }

#pragma unroll
    for (int i = 0; i < 8; i++) {
        int gm = bm + tRow + i;
        if (gm < N_NODES) {
            *(float4*)(g_G + (size_t)gm * N + bn + tCol) =
                make_float4(acc[i][0], acc[i][1], acc[i][2], acc[i][3]);
            *(float4*)(g_G + (size_t)gm * N + bn + tCol + 4) =
                make_float4(acc[i][4], acc[i][5], acc[i][6], acc[i][7]);
        }
    }
}

// ---------------- CSR gather aggregation: one warp per node ----------------
// AGG[n] = b + dinv[n]^2 * G[n] + sum_{e in row(n)} w_e * G[src_e]
__global__ __launch_bounds__(256) void k_gather(const float* __restrict__ bias) {
    int t = blockIdx.x * blockDim.x + threadIdx.x;
    int node = t >> 5;
    int lane = t & 31;
    if (node >= N_NODES) return;

    int beg = g_rowstart[node];
    int end = g_rowstart[node + 1];
    float di = g_dinv[node];
    float wself = di * di;

    const float4* grow = (const float4*)(g_G + (size_t)node * HID);
    const float4* b4 = (const float4*)bias;

    float4 acc0 = b4[lane];
    float4 acc1 = b4[lane + 32];
    float4 v0 = grow[lane];
    float4 v1 = grow[lane + 32];
    acc0.x += wself * v0.x; acc0.y += wself * v0.y;
    acc0.z += wself * v0.z; acc0.w += wself * v0.w;
    acc1.x += wself * v1.x; acc1.y += wself * v1.y;
    acc1.z += wself * v1.z; acc1.w += wself * v1.w;

    for (int e = beg; e < end; e++) {
        int s = g_esrc[e];
        float w = g_ew[e];
        const float4* gs = (const float4*)(g_G + (size_t)s * HID);
        float4 u0 = gs[lane];
        float4 u1 = gs[lane + 32];
        acc0.x += w * u0.x; acc0.y += w * u0.y;
        acc0.z += w * u0.z; acc0.w += w * u0.w;
        acc1.x += w * u1.x; acc1.y += w * u1.y;
        acc1.z += w * u1.z; acc1.w += w * u1.w;
    }

    float4* arow = (float4*)(g_AGG + (size_t)node * HID);
    arow[lane] = acc0;
    arow[lane + 32] = acc1;
}

// ---------------- readout: warp per node ----------------
__global__ void k_readout(const float* __restrict__ Wout,
                          const float* __restrict__ bout, float* __restrict__ out) {
    int t = blockIdx.x * blockDim.x + threadIdx.x;
    int node = t >> 5;
    int lane = t & 31;
    if (node >= N_NODES) return;
    const float* row = g_AGG + (size_t)node * HID;
    float acc = 0.0f;
#pragma unroll
    for (int j = lane; j < HID; j += 32)
        acc += fmaxf(row[j], 0.0f) * Wout[j];
#pragma unroll
    for (int o = 16; o; o >>= 1) acc += __shfl_xor_sync(0xffffffffu, acc, o);
    if (lane == 0) out[node] = acc + bout[0];
}

extern "C" void kernel_launch(void* const* d_in, const int* in_sizes, int n_in,
                              void* d_out, int out_size) {
    const float* x = (const float*)d_in[0];
    const int* ei = (const int*)d_in[1];  // int32 (JAX x64 disabled)
    const float* W0 = (const float*)d_in[2];
    const float* b0 = (const float*)d_in[3];
    const float* W1 = (const float*)d_in[4];
    const float* b1 = (const float*)d_in[5];
    const float* W2 = (const float*)d_in[6];
    const float* b2 = (const float*)d_in[7];
    const float* Wout = (const float*)d_in[8];
    const float* bout = (const float*)d_in[9];
    float* out = (float*)d_out;

    // CSR build (by dst) + normalization
    k_zero_deg<<<(N_NODES + 255) / 256, 256>>>();
    k_deg_accum<<<(N_EDGES + 255) / 256, 256>>>(ei);
    k_dinv<<<(N_NODES + 255) / 256, 256>>>();
    k_scan1<<<SCAN_BLOCKS, 256>>>();
    k_scan2<<<1, 256>>>();
    k_scan3<<<SCAN_BLOCKS, 256>>>();
    k_fill<<<(N_EDGES + 255) / 256, 256>>>(ei);

    dim3 gemmGrid(HID / 128, (N_NODES + 127) / 128);
    const int gatherBlocks = (N_NODES * 32 + 255) / 256;

    // layer 0
    k_sgemm<true><<<gemmGrid, 256>>>(x, W0);
    k_gather<<<gatherBlocks, 256>>>(b0);
    // layer 1
    k_sgemm<false><<<gemmGrid, 256>>>(nullptr, W1);
    k_gather<<<gatherBlocks, 256>>>(b1);
    // layer 2
    k_sgemm<false><<<gemmGrid, 256>>>(nullptr, W2);
    k_gather<<<gatherBlocks, 256>>>(b2);
    // readout
    k_readout<<<(N_NODES * 32 + 255) / 256, 256>>>(Wout, bout, out);
}

// round 8
// speedup vs baseline: 3.7787x; 1.5260x over previous
#include <cuda_runtime.h>
#include <cuda_fp16.h>
#include <cstdint>

#define N_NODES 50000
#define N_EDGES 800000
#define IN_CH 512
#define HID 256
#define SCAN_BLOCKS ((N_NODES + 255) / 256)  // 196

// ---------------- scratch (__device__ globals; never passed as kernel args) --
__device__ float g_G[(size_t)N_NODES * HID];
__device__ float g_AGG[(size_t)N_NODES * HID];
__device__ float g_dinv[N_NODES];
__device__ int   g_degi[N_NODES];
__device__ int   g_rowstart[N_NODES + 1];
__device__ int   g_cursor[N_NODES];
__device__ int   g_esrc[N_EDGES];
__device__ float g_ew[N_EDGES];
__device__ int   g_part[SCAN_BLOCKS];
// W^T split (fp16 hi/lo), [N][K] layout, 16B-aligned for uint4 loads
__device__ __align__(16) __half g_WThi0[HID * IN_CH];
__device__ __align__(16) __half g_WTlo0[HID * IN_CH];
__device__ __align__(16) __half g_WThi1[HID * HID];
__device__ __align__(16) __half g_WTlo1[HID * HID];
__device__ __align__(16) __half g_WThi2[HID * HID];
__device__ __align__(16) __half g_WTlo2[HID * HID];

// ---------------- CSR build ----------------
__global__ void k_zero_deg() {
    int i = blockIdx.x * blockDim.x + threadIdx.x;
    if (i < N_NODES) g_degi[i] = 0;
}
__global__ void k_deg_accum(const int* __restrict__ ei) {
    int i = blockIdx.x * blockDim.x + threadIdx.x;
    if (i < N_EDGES) {
        int d = ei[N_EDGES + i];
        if ((unsigned)d < N_NODES) atomicAdd(&g_degi[d], 1);
    }
}
__global__ void k_dinv() {
    int i = blockIdx.x * blockDim.x + threadIdx.x;
    if (i < N_NODES) g_dinv[i] = rsqrtf(1.0f + (float)g_degi[i]);
}
__global__ void k_scan1() {
    __shared__ int sh[256];
    int i = blockIdx.x * 256 + threadIdx.x;
    sh[threadIdx.x] = (i < N_NODES) ? g_degi[i] : 0;
    __syncthreads();
    for (int o = 128; o; o >>= 1) {
        if (threadIdx.x < o) sh[threadIdx.x] += sh[threadIdx.x + o];
        __syncthreads();
    }
    if (threadIdx.x == 0) g_part[blockIdx.x] = sh[0];
}
__global__ void k_scan2() {
    __shared__ int sh[256];
    int t = threadIdx.x;
    sh[t] = (t < SCAN_BLOCKS) ? g_part[t] : 0;
    __syncthreads();
    for (int o = 1; o < 256; o <<= 1) {
        int v = (t >= o) ? sh[t - o] : 0;
        __syncthreads();
        sh[t] += v;
        __syncthreads();
    }
    if (t < SCAN_BLOCKS) g_part[t] = (t == 0) ? 0 : sh[t - 1];
}
__global__ void k_scan3() {
    __shared__ int sh[256];
    int t = threadIdx.x;
    int i = blockIdx.x * 256 + t;
    int v = (i < N_NODES) ? g_degi[i] : 0;
    sh[t] = v;
    __syncthreads();
    for (int o = 1; o < 256; o <<= 1) {
        int u = (t >= o) ? sh[t - o] : 0;
        __syncthreads();
        sh[t] += u;
        __syncthreads();
    }
    int incl = sh[t];
    int base = g_part[blockIdx.x];
    if (i < N_NODES) {
        int rs = base + incl - v;
        g_rowstart[i] = rs;
        g_cursor[i] = rs;
        if (i == N_NODES - 1) g_rowstart[N_NODES] = base + incl;
    }
}
__global__ void k_fill(const int* __restrict__ ei) {
    int e = blockIdx.x * blockDim.x + threadIdx.x;
    if (e >= N_EDGES) return;
    int s = ei[e];
    int d = ei[N_EDGES + e];
    if ((unsigned)s >= N_NODES || (unsigned)d >= N_NODES) return;
    int pos = atomicAdd(&g_cursor[d], 1);
    g_esrc[pos] = s;
    g_ew[pos] = g_dinv[s] * g_dinv[d];
}

// ---------------- W^T fp16 hi/lo split prep (globals referenced in-kernel) ---
template <int L>
__global__ void k_prep(const float* __restrict__ W) {
    constexpr int K = (L == 0) ? IN_CH : HID;
    __half* WThi = (L == 0) ? g_WThi0 : (L == 1 ? g_WThi1 : g_WThi2);
    __half* WTlo = (L == 0) ? g_WTlo0 : (L == 1 ? g_WTlo1 : g_WTlo2);
    int i = blockIdx.x * blockDim.x + threadIdx.x;
    if (i >= K * HID) return;
    int k = i / HID, n = i % HID;
    float v = W[i];  // W[k][n]
    __half hi = __float2half_rn(v);
    __half lo = __float2half_rn(v - __half2float(hi));
    WThi[(size_t)n * K + k] = hi;
    WTlo[(size_t)n * K + k] = lo;
}

// ---------------- fp16 3x-split mma.sync GEMM: g_G = (relu?)A @ W ------------
// CTA tile 128x128, BK=32, 8 warps (warp tile 64x32), double-buffered smem.
// smem stage: Ah[128][40] fp16 | Al | Bh[128][40] | Bl  (40 = 32 + 8 pad)
#define ROWB 80            // bytes per padded row (40 fp16)
#define TILE_BYTES 10240   // 128 * 80
#define STAGE_BYTES (4 * TILE_BYTES)

#define MMA16816(c, a, b) \
    asm volatile("mma.sync.aligned.m16n8k16.row.col.f32.f16.f16.f32 " \
        "{%0,%1,%2,%3},{%4,%5,%6,%7},{%8,%9},{%0,%1,%2,%3};" \
        : "+f"((c)[0]), "+f"((c)[1]), "+f"((c)[2]), "+f"((c)[3]) \
        : "r"((a)[0]), "r"((a)[1]), "r"((a)[2]), "r"((a)[3]), \
          "r"((b)[0]), "r"((b)[1]))

template <int L>
__global__ __launch_bounds__(256) void k_mma(const float* __restrict__ Ax) {
    constexpr int K = (L == 0) ? IN_CH : HID;
    constexpr int NT = K / 32;
    const float* A = (L == 0) ? Ax : (const float*)g_AGG;
    const __half* Bhg = (L == 0) ? g_WThi0 : (L == 1 ? g_WThi1 : g_WThi2);
    const __half* Blg = (L == 0) ? g_WTlo0 : (L == 1 ? g_WTlo1 : g_WTlo2);

    extern __shared__ char sm[];
    const int tid = threadIdx.x;
    const int lane = tid & 31;
    const int wid = tid >> 5;
    const int wm = wid >> 2;       // 0..1  -> m base wm*64
    const int wn = wid & 3;        // 0..3  -> n base wn*32
    const int bm = blockIdx.y * 128;
    const int bn = blockIdx.x * 128;
    const int g = lane >> 2;       // 0..7
    const int tig = lane & 3;      // 0..3

    float acc[4][4][4];
#pragma unroll
    for (int i = 0; i < 4; i++)
#pragma unroll
        for (int j = 0; j < 4; j++)
#pragma unroll
            for (int q = 0; q < 4; q++) acc[i][j][q] = 0.0f;

    float4 va[4];
    uint4 vb[4];

    auto ldA = [&](int t) {
#pragma unroll
        for (int j = 0; j < 4; j++) {
            int i = tid + 256 * j;
            int row = i >> 3, colg = i & 7;
            int gm = bm + row;
            float4 v = make_float4(0.f, 0.f, 0.f, 0.f);
            if (gm < N_NODES) v = *(const float4*)(A + (size_t)gm * K + t * 32 + colg * 4);
            if (L != 0) {
                v.x = fmaxf(v.x, 0.f); v.y = fmaxf(v.y, 0.f);
                v.z = fmaxf(v.z, 0.f); v.w = fmaxf(v.w, 0.f);
            }
            va[j] = v;
        }
    };
    auto ldB = [&](int t) {
#pragma unroll
        for (int j = 0; j < 2; j++) {
            int i = tid + 256 * j;
            int row = i >> 2, colg = i & 3;
            size_t gi = (size_t)(bn + row) * K + t * 32 + colg * 8;
            vb[j] = *(const uint4*)(Bhg + gi);
            vb[j + 2] = *(const uint4*)(Blg + gi);
        }
    };
    auto stage = [&](int buf) {
        char* Ah = sm + buf * STAGE_BYTES;
        char* Al = Ah + TILE_BYTES;
        char* Bh = Ah + 2 * TILE_BYTES;
        char* Bl = Ah + 3 * TILE_BYTES;
#pragma unroll
        for (int j = 0; j < 4; j++) {
            int i = tid + 256 * j;
            int row = i >> 3, col = (i & 7) * 4;
            float4 v = va[j];
            __half2 h01 = __floats2half2_rn(v.x, v.y);
            __half2 h23 = __floats2half2_rn(v.z, v.w);
            __half2 l01 = __floats2half2_rn(v.x - __half2float(__low2half(h01)),
                                            v.y - __half2float(__high2half(h01)));
            __half2 l23 = __floats2half2_rn(v.z - __half2float(__low2half(h23)),
                                            v.w - __half2float(__high2half(h23)));
            char* pa = Ah + row * ROWB + col * 2;
            *(uint32_t*)pa = *(uint32_t*)&h01;
            *(uint32_t*)(pa + 4) = *(uint32_t*)&h23;
            char* pl = Al + row * ROWB + col * 2;
            *(uint32_t*)pl = *(uint32_t*)&l01;
            *(uint32_t*)(pl + 4) = *(uint32_t*)&l23;
        }
#pragma unroll
        for (int j = 0; j < 2; j++) {
            int i = tid + 256 * j;
            int row = i >> 2, col = (i & 3) * 8;
            *(uint4*)(Bh + row * ROWB + col * 2) = vb[j];
            *(uint4*)(Bl + row * ROWB + col * 2) = vb[j + 2];
        }
    };
    auto compute = [&](int buf) {
        const char* Ah = sm + buf * STAGE_BYTES;
        const char* Al = Ah + TILE_BYTES;
        const char* Bh = Ah + 2 * TILE_BYTES;
        const char* Bl = Ah + 3 * TILE_BYTES;
#pragma unroll
        for (int ks = 0; ks < 2; ks++) {
            const int kb = (ks * 16 + 2 * tig) * 2;  // byte offset of k-pair
            uint32_t ah[4][4], al[4][4], bh[4][2], bl[4][2];
#pragma unroll
            for (int mt = 0; mt < 4; mt++) {
                int r0 = wm * 64 + mt * 16 + g;
                const char* p = Ah + r0 * ROWB + kb;
                ah[mt][0] = *(const uint32_t*)p;
                ah[mt][1] = *(const uint32_t*)(p + 8 * ROWB);
                ah[mt][2] = *(const uint32_t*)(p + 16);
                ah[mt][3] = *(const uint32_t*)(p + 8 * ROWB + 16);
                const char* q = Al + r0 * ROWB + kb;
                al[mt][0] = *(const uint32_t*)q;
                al[mt][1] = *(const uint32_t*)(q + 8 * ROWB);
                al[mt][2] = *(const uint32_t*)(q + 16);
                al[mt][3] = *(const uint32_t*)(q + 8 * ROWB + 16);
            }
#pragma unroll
            for (int nt = 0; nt < 4; nt++) {
                int n0 = wn * 32 + nt * 8 + g;
                const char* p = Bh + n0 * ROWB + kb;
                bh[nt][0] = *(const uint32_t*)p;
                bh[nt][1] = *(const uint32_t*)(p + 16);
                const char* q = Bl + n0 * ROWB + kb;
                bl[nt][0] = *(const uint32_t*)q;
                bl[nt][1] = *(const uint32_t*)(q + 16);
            }
#pragma unroll
            for (int mt = 0; mt < 4; mt++)
#pragma unroll
                for (int nt = 0; nt < 4; nt++) {
                    MMA16816(acc[mt][nt], ah[mt], bh[nt]);
                    MMA16816(acc[mt][nt], ah[mt], bl[nt]);
                    MMA16816(acc[mt][nt], al[mt], bh[nt]);
                }
        }
    };

    ldA(0); ldB(0);
    stage(0);
    __syncthreads();

    int buf = 0;
    for (int t = 0; t < NT; t++) {
        if (t + 1 < NT) { ldA(t + 1); ldB(t + 1); }
        compute(buf);
        if (t + 1 < NT) {
            stage(buf ^ 1);
            __syncthreads();
            buf ^= 1;
        }
    }

    // epilogue
#pragma unroll
    for (int mt = 0; mt < 4; mt++) {
        int row = bm + wm * 64 + mt * 16 + g;
#pragma unroll
        for (int nt = 0; nt < 4; nt++) {
            int col = bn + wn * 32 + nt * 8 + 2 * tig;
            if (row < N_NODES)
                *(float2*)(g_G + (size_t)row * HID + col) =
                    make_float2(acc[mt][nt][0], acc[mt][nt][1]);
            if (row + 8 < N_NODES)
                *(float2*)(g_G + (size_t)(row + 8) * HID + col) =
                    make_float2(acc[mt][nt][2], acc[mt][nt][3]);
        }
    }
}

// ---------------- CSR gather aggregation: one warp per node ----------------
__global__ __launch_bounds__(256) void k_gather(const float* __restrict__ bias) {
    int t = blockIdx.x * blockDim.x + threadIdx.x;
    int node = t >> 5;
    int lane = t & 31;
    if (node >= N_NODES) return;

    int beg = g_rowstart[node];
    int end = g_rowstart[node + 1];
    float di = g_dinv[node];
    float wself = di * di;

    const float4* grow = (const float4*)(g_G + (size_t)node * HID);
    const float4* b4 = (const float4*)bias;

    float4 acc0 = b4[lane];
    float4 acc1 = b4[lane + 32];
    float4 v0 = grow[lane];
    float4 v1 = grow[lane + 32];
    acc0.x += wself * v0.x; acc0.y += wself * v0.y;
    acc0.z += wself * v0.z; acc0.w += wself * v0.w;
    acc1.x += wself * v1.x; acc1.y += wself * v1.y;
    acc1.z += wself * v1.z; acc1.w += wself * v1.w;

    for (int e = beg; e < end; e++) {
        int s = g_esrc[e];
        float w = g_ew[e];
        const float4* gs = (const float4*)(g_G + (size_t)s * HID);
        float4 u0 = gs[lane];
        float4 u1 = gs[lane + 32];
        acc0.x += w * u0.x; acc0.y += w * u0.y;
        acc0.z += w * u0.z; acc0.w += w * u0.w;
        acc1.x += w * u1.x; acc1.y += w * u1.y;
        acc1.z += w * u1.z; acc1.w += w * u1.w;
    }

    float4* arow = (float4*)(g_AGG + (size_t)node * HID);
    arow[lane] = acc0;
    arow[lane + 32] = acc1;
}

// ---------------- readout: warp per node ----------------
__global__ void k_readout(const float* __restrict__ Wout,
                          const float* __restrict__ bout, float* __restrict__ out) {
    int t = blockIdx.x * blockDim.x + threadIdx.x;
    int node = t >> 5;
    int lane = t & 31;
    if (node >= N_NODES) return;
    const float* row = g_AGG + (size_t)node * HID;
    float acc = 0.0f;
#pragma unroll
    for (int j = lane; j < HID; j += 32)
        acc += fmaxf(row[j], 0.0f) * Wout[j];
#pragma unroll
    for (int o = 16; o; o >>= 1) acc += __shfl_xor_sync(0xffffffffu, acc, o);
    if (lane == 0) out[node] = acc + bout[0];
}

extern "C" void kernel_launch(void* const* d_in, const int* in_sizes, int n_in,
                              void* d_out, int out_size) {
    const float* x = (const float*)d_in[0];
    const int* ei = (const int*)d_in[1];
    const float* W0 = (const float*)d_in[2];
    const float* b0 = (const float*)d_in[3];
    const float* W1 = (const float*)d_in[4];
    const float* b1 = (const float*)d_in[5];
    const float* W2 = (const float*)d_in[6];
    const float* b2 = (const float*)d_in[7];
    const float* Wout = (const float*)d_in[8];
    const float* bout = (const float*)d_in[9];
    float* out = (float*)d_out;

    const int SMEM = 2 * STAGE_BYTES;  // 80 KB
    cudaFuncSetAttribute(k_mma<0>, cudaFuncAttributeMaxDynamicSharedMemorySize, SMEM);
    cudaFuncSetAttribute(k_mma<1>, cudaFuncAttributeMaxDynamicSharedMemorySize, SMEM);
    cudaFuncSetAttribute(k_mma<2>, cudaFuncAttributeMaxDynamicSharedMemorySize, SMEM);

    // CSR build + normalization
    k_zero_deg<<<(N_NODES + 255) / 256, 256>>>();
    k_deg_accum<<<(N_EDGES + 255) / 256, 256>>>(ei);
    k_dinv<<<(N_NODES + 255) / 256, 256>>>();
    k_scan1<<<SCAN_BLOCKS, 256>>>();
    k_scan2<<<1, 256>>>();
    k_scan3<<<SCAN_BLOCKS, 256>>>();
    k_fill<<<(N_EDGES + 255) / 256, 256>>>(ei);

    // weight splits (globals referenced inside the kernels)
    k_prep<0><<<(IN_CH * HID + 255) / 256, 256>>>(W0);
    k_prep<1><<<(HID * HID + 255) / 256, 256>>>(W1);
    k_prep<2><<<(HID * HID + 255) / 256, 256>>>(W2);

    dim3 grid(HID / 128, (N_NODES + 127) / 128);  // (2, 391)
    const int gatherBlocks = (N_NODES * 32 + 255) / 256;

    // layer 0
    k_mma<0><<<grid, 256, SMEM>>>(x);
    k_gather<<<gatherBlocks, 256>>>(b0);
    // layer 1
    k_mma<1><<<grid, 256, SMEM>>>(nullptr);
    k_gather<<<gatherBlocks, 256>>>(b1);
    // layer 2
    k_mma<2><<<grid, 256, SMEM>>>(nullptr);
    k_gather<<<gatherBlocks, 256>>>(b2);
    // readout
    k_readout<<<(N_NODES * 32 + 255) / 256, 256>>>(Wout, bout, out);
}

// round 9
// speedup vs baseline: 4.3460x; 1.1501x over previous
#include <cuda_runtime.h>
#include <cuda_fp16.h>
#include <cstdint>

#define N_NODES 50000
#define N_EDGES 800000
#define IN_CH 512
#define HID 256
#define SCAN_BLOCKS ((N_NODES + 255) / 256)  // 196

// ---------------- scratch (__device__ globals; never passed as kernel args) --
__device__ float g_G[(size_t)N_NODES * HID];
__device__ float g_dinv[N_NODES];
__device__ int   g_degi[N_NODES];
__device__ int   g_rowstart[N_NODES + 1];
__device__ int   g_cursor[N_NODES];
__device__ int   g_esrc[N_EDGES];
__device__ float g_ew[N_EDGES];
__device__ int   g_part[SCAN_BLOCKS];
// A operands pre-split to fp16 hi/lo
__device__ __align__(16) __half g_xhi[(size_t)N_NODES * IN_CH];
__device__ __align__(16) __half g_xlo[(size_t)N_NODES * IN_CH];
__device__ __align__(16) __half g_hhi[(size_t)N_NODES * HID];  // relu(AGG) hi
__device__ __align__(16) __half g_hlo[(size_t)N_NODES * HID];  // relu(AGG) lo
// W^T split (fp16 hi/lo), [N][K] layout
__device__ __align__(16) __half g_WThi0[HID * IN_CH];
__device__ __align__(16) __half g_WTlo0[HID * IN_CH];
__device__ __align__(16) __half g_WThi1[HID * HID];
__device__ __align__(16) __half g_WTlo1[HID * HID];
__device__ __align__(16) __half g_WThi2[HID * HID];
__device__ __align__(16) __half g_WTlo2[HID * HID];

// ---------------- small PTX helpers ----------------
__device__ __forceinline__ uint32_t smem_u32(const void* p) {
    uint32_t a;
    asm("{ .reg .u64 t; cvta.to.shared.u64 t, %1; cvt.u32.u64 %0, t; }" : "=r"(a) : "l"(p));
    return a;
}
__device__ __forceinline__ void cp16(uint32_t dst, const void* src, int sz) {
    asm volatile("cp.async.cg.shared.global [%0], [%1], 16, %2;"
                 :: "r"(dst), "l"(src), "r"(sz));
}
#define CP_COMMIT() asm volatile("cp.async.commit_group;" ::: "memory")
#define CP_WAIT0()  asm volatile("cp.async.wait_group 0;" ::: "memory")
#define LDSM4(r0, r1, r2, r3, addr) \
    asm volatile("ldmatrix.sync.aligned.m8n8.x4.shared.b16 {%0,%1,%2,%3}, [%4];" \
                 : "=r"(r0), "=r"(r1), "=r"(r2), "=r"(r3) : "r"(addr))
#define MMA16816(c, a, b) \
    asm volatile("mma.sync.aligned.m16n8k16.row.col.f32.f16.f16.f32 " \
        "{%0,%1,%2,%3},{%4,%5,%6,%7},{%8,%9},{%0,%1,%2,%3};" \
        : "+f"((c)[0]), "+f"((c)[1]), "+f"((c)[2]), "+f"((c)[3]) \
        : "r"((a)[0]), "r"((a)[1]), "r"((a)[2]), "r"((a)[3]), \
          "r"((b)[0]), "r"((b)[1]))

// ---------------- CSR build ----------------
__global__ void k_zero_deg() {
    int i = blockIdx.x * blockDim.x + threadIdx.x;
    if (i < N_NODES) g_degi[i] = 0;
}
__global__ void k_deg_accum(const int* __restrict__ ei) {
    int i = blockIdx.x * blockDim.x + threadIdx.x;
    if (i < N_EDGES) {
        int d = ei[N_EDGES + i];
        if ((unsigned)d < N_NODES) atomicAdd(&g_degi[d], 1);
    }
}
__global__ void k_dinv() {
    int i = blockIdx.x * blockDim.x + threadIdx.x;
    if (i < N_NODES) g_dinv[i] = rsqrtf(1.0f + (float)g_degi[i]);
}
__global__ void k_scan1() {
    __shared__ int sh[256];
    int i = blockIdx.x * 256 + threadIdx.x;
    sh[threadIdx.x] = (i < N_NODES) ? g_degi[i] : 0;
    __syncthreads();
    for (int o = 128; o; o >>= 1) {
        if (threadIdx.x < o) sh[threadIdx.x] += sh[threadIdx.x + o];
        __syncthreads();
    }
    if (threadIdx.x == 0) g_part[blockIdx.x] = sh[0];
}
__global__ void k_scan2() {
    __shared__ int sh[256];
    int t = threadIdx.x;
    sh[t] = (t < SCAN_BLOCKS) ? g_part[t] : 0;
    __syncthreads();
    for (int o = 1; o < 256; o <<= 1) {
        int v = (t >= o) ? sh[t - o] : 0;
        __syncthreads();
        sh[t] += v;
        __syncthreads();
    }
    if (t < SCAN_BLOCKS) g_part[t] = (t == 0) ? 0 : sh[t - 1];
}
__global__ void k_scan3() {
    __shared__ int sh[256];
    int t = threadIdx.x;
    int i = blockIdx.x * 256 + t;
    int v = (i < N_NODES) ? g_degi[i] : 0;
    sh[t] = v;
    __syncthreads();
    for (int o = 1; o < 256; o <<= 1) {
        int u = (t >= o) ? sh[t - o] : 0;
        __syncthreads();
        sh[t] += u;
        __syncthreads();
    }
    int incl = sh[t];
    int base = g_part[blockIdx.x];
    if (i < N_NODES) {
        int rs = base + incl - v;
        g_rowstart[i] = rs;
        g_cursor[i] = rs;
        if (i == N_NODES - 1) g_rowstart[N_NODES] = base + incl;
    }
}
__global__ void k_fill(const int* __restrict__ ei) {
    int e = blockIdx.x * blockDim.x + threadIdx.x;
    if (e >= N_EDGES) return;
    int s = ei[e];
    int d = ei[N_EDGES + e];
    if ((unsigned)s >= N_NODES || (unsigned)d >= N_NODES) return;
    int pos = atomicAdd(&g_cursor[d], 1);
    g_esrc[pos] = s;
    g_ew[pos] = g_dinv[s] * g_dinv[d];
}

// ---------------- prep: split x and W^T into fp16 hi/lo ----------------
__global__ void k_prepx(const float* __restrict__ x) {
    int i = blockIdx.x * blockDim.x + threadIdx.x;  // float4 index
    if (i >= N_NODES * IN_CH / 4) return;
    float4 v = ((const float4*)x)[i];
    __half2 h01 = __floats2half2_rn(v.x, v.y);
    __half2 h23 = __floats2half2_rn(v.z, v.w);
    __half2 l01 = __floats2half2_rn(v.x - __half2float(__low2half(h01)),
                                    v.y - __half2float(__high2half(h01)));
    __half2 l23 = __floats2half2_rn(v.z - __half2float(__low2half(h23)),
                                    v.w - __half2float(__high2half(h23)));
    ((uint2*)g_xhi)[i] = make_uint2(*(uint32_t*)&h01, *(uint32_t*)&h23);
    ((uint2*)g_xlo)[i] = make_uint2(*(uint32_t*)&l01, *(uint32_t*)&l23);
}
template <int L>
__global__ void k_prep(const float* __restrict__ W) {
    constexpr int K = (L == 0) ? IN_CH : HID;
    __half* WThi = (L == 0) ? g_WThi0 : (L == 1 ? g_WThi1 : g_WThi2);
    __half* WTlo = (L == 0) ? g_WTlo0 : (L == 1 ? g_WTlo1 : g_WTlo2);
    int i = blockIdx.x * blockDim.x + threadIdx.x;
    if (i >= K * HID) return;
    int k = i / HID, n = i % HID;
    float v = W[i];  // W[k][n]
    __half hi = __float2half_rn(v);
    __half lo = __float2half_rn(v - __half2float(hi));
    WThi[(size_t)n * K + k] = hi;
    WTlo[(size_t)n * K + k] = lo;
}

// ---------------- fp16 3x-split mma GEMM, cp.async + ldmatrix ----------------
// CTA tile 128x128, BK=32, 8 warps (warp tile 64x32), double-buffered smem.
// stage: Ah[128][40] | Al | Bh[128][40] | Bl  (40 fp16 = 32 + pad; ROWB=80B)
#define ROWB 80
#define TILE_BYTES 10240       // 128 * 80
#define STAGE_BYTES (4 * TILE_BYTES)

template <int L>
__global__ __launch_bounds__(256) void k_mma() {
    constexpr int K = (L == 0) ? IN_CH : HID;
    constexpr int NT = K / 32;
    const __half* Ahg = (L == 0) ? g_xhi : g_hhi;
    const __half* Alg = (L == 0) ? g_xlo : g_hlo;
    const __half* Bhg = (L == 0) ? g_WThi0 : (L == 1 ? g_WThi1 : g_WThi2);
    const __half* Blg = (L == 0) ? g_WTlo0 : (L == 1 ? g_WTlo1 : g_WTlo2);

    extern __shared__ __align__(128) char sm[];
    const uint32_t smb = smem_u32(sm);
    const int tid = threadIdx.x;
    const int lane = tid & 31;
    const int wid = tid >> 5;
    const int wm = wid >> 2;   // 0..1 -> m base wm*64
    const int wn = wid & 3;    // 0..3 -> n base wn*32
    const int bm = blockIdx.y * 128;
    const int bn = blockIdx.x * 128;
    const int g = lane >> 2;
    const int tig = lane & 3;
    const int grp = lane >> 3;
    const int rr = lane & 7;

    float acc[4][4][4];
#pragma unroll
    for (int i = 0; i < 4; i++)
#pragma unroll
        for (int j = 0; j < 4; j++)
#pragma unroll
            for (int q = 0; q < 4; q++) acc[i][j][q] = 0.0f;

    // per-thread chunk mapping for cp.async (8 x 16B per thread per stage)
    auto issue_loads = [&](int t, int buf) {
        uint32_t base = smb + buf * STAGE_BYTES;
#pragma unroll
        for (int j = 0; j < 8; j++) {
            int c = tid + 256 * j;        // 0..2047
            int tile = c >> 9;            // 0..3
            int cc = c & 511;
            int row = cc >> 2;
            int col16 = cc & 3;
            uint32_t dst = base + tile * TILE_BYTES + row * ROWB + col16 * 16;
            const __half* src;
            int sz = 16;
            if (tile < 2) {
                int gm = bm + row;
                if (gm >= N_NODES) { gm = 0; sz = 0; }
                src = (tile ? Alg : Ahg) + (size_t)gm * K + t * 32 + col16 * 8;
            } else {
                int gn = bn + row;
                src = (tile == 3 ? Blg : Bhg) + (size_t)gn * K + t * 32 + col16 * 8;
            }
            cp16(dst, src, sz);
        }
        CP_COMMIT();
    };

    // ldmatrix row address components
    const uint32_t a_rowoff = (uint32_t)(wm * 64 + ((grp & 1) << 3) + rr) * ROWB
                              + ((grp >> 1) << 4);
    const uint32_t b_rowoff = (uint32_t)(wn * 32 + ((grp >> 1) << 3) + rr) * ROWB
                              + ((grp & 1) << 4);

    auto compute = [&](int buf) {
        uint32_t tb = smb + buf * STAGE_BYTES;
#pragma unroll
        for (int ks = 0; ks < 2; ks++) {
            const uint32_t kbB = ks * 32;
            uint32_t ah[4][4], al[4][4], bh[4][2], bl[4][2];
#pragma unroll
            for (int mt = 0; mt < 4; mt++) {
                uint32_t addr = tb + a_rowoff + mt * (16 * ROWB) + kbB;
                LDSM4(ah[mt][0], ah[mt][1], ah[mt][2], ah[mt][3], addr);
                LDSM4(al[mt][0], al[mt][1], al[mt][2], al[mt][3], addr + TILE_BYTES);
            }
#pragma unroll
            for (int np = 0; np < 2; np++) {
                uint32_t addr = tb + 2 * TILE_BYTES + b_rowoff + np * (16 * ROWB) + kbB;
                LDSM4(bh[2 * np][0], bh[2 * np][1], bh[2 * np + 1][0], bh[2 * np + 1][1], addr);
                LDSM4(bl[2 * np][0], bl[2 * np][1], bl[2 * np + 1][0], bl[2 * np + 1][1],
                      addr + TILE_BYTES);
            }
#pragma unroll
            for (int mt = 0; mt < 4; mt++)
#pragma unroll
                for (int nt = 0; nt < 4; nt++) {
                    MMA16816(acc[mt][nt], ah[mt], bh[nt]);
                    MMA16816(acc[mt][nt], ah[mt], bl[nt]);
                    MMA16816(acc[mt][nt], al[mt], bh[nt]);
                }
        }
    };

    issue_loads(0, 0);
    CP_WAIT0();
    __syncthreads();

    int buf = 0;
    for (int t = 0; t < NT; t++) {
        if (t + 1 < NT) issue_loads(t + 1, buf ^ 1);
        compute(buf);
        if (t + 1 < NT) {
            CP_WAIT0();
            __syncthreads();
            buf ^= 1;
        }
    }

    // epilogue: fp32 G
#pragma unroll
    for (int mt = 0; mt < 4; mt++) {
        int row = bm + wm * 64 + mt * 16 + g;
#pragma unroll
        for (int nt = 0; nt < 4; nt++) {
            int col = bn + wn * 32 + nt * 8 + 2 * tig;
            if (row < N_NODES)
                *(float2*)(g_G + (size_t)row * HID + col) =
                    make_float2(acc[mt][nt][0], acc[mt][nt][1]);
            if (row + 8 < N_NODES)
                *(float2*)(g_G + (size_t)(row + 8) * HID + col) =
                    make_float2(acc[mt][nt][2], acc[mt][nt][3]);
        }
    }
}

// ---------------- CSR gather: AGG -> relu -> fp16 hi/lo split ----------------
__global__ __launch_bounds__(256) void k_gather(const float* __restrict__ bias) {
    int t = blockIdx.x * blockDim.x + threadIdx.x;
    int node = t >> 5;
    int lane = t & 31;
    if (node >= N_NODES) return;

    int beg = g_rowstart[node];
    int end = g_rowstart[node + 1];
    float di = g_dinv[node];
    float wself = di * di;

    const float4* grow = (const float4*)(g_G + (size_t)node * HID);
    const float4* b4 = (const float4*)bias;

    float4 acc0 = b4[lane];
    float4 acc1 = b4[lane + 32];
    float4 v0 = grow[lane];
    float4 v1 = grow[lane + 32];
    acc0.x += wself * v0.x; acc0.y += wself * v0.y;
    acc0.z += wself * v0.z; acc0.w += wself * v0.w;
    acc1.x += wself * v1.x; acc1.y += wself * v1.y;
    acc1.z += wself * v1.z; acc1.w += wself * v1.w;

    for (int e = beg; e < end; e++) {
        int s = g_esrc[e];
        float w = g_ew[e];
        const float4* gs = (const float4*)(g_G + (size_t)s * HID);
        float4 u0 = gs[lane];
        float4 u1 = gs[lane + 32];
        acc0.x += w * u0.x; acc0.y += w * u0.y;
        acc0.z += w * u0.z; acc0.w += w * u0.w;
        acc1.x += w * u1.x; acc1.y += w * u1.y;
        acc1.z += w * u1.z; acc1.w += w * u1.w;
    }

    // relu + fp16 hi/lo split
    auto emit = [&](float4 a, int colbase) {
        a.x = fmaxf(a.x, 0.f); a.y = fmaxf(a.y, 0.f);
        a.z = fmaxf(a.z, 0.f); a.w = fmaxf(a.w, 0.f);
        __half2 h01 = __floats2half2_rn(a.x, a.y);
        __half2 h23 = __floats2half2_rn(a.z, a.w);
        __half2 l01 = __floats2half2_rn(a.x - __half2float(__low2half(h01)),
                                        a.y - __half2float(__high2half(h01)));
        __half2 l23 = __floats2half2_rn(a.z - __half2float(__low2half(h23)),
                                        a.w - __half2float(__high2half(h23)));
        size_t o = (size_t)node * HID + colbase;
        *(uint2*)(g_hhi + o) = make_uint2(*(uint32_t*)&h01, *(uint32_t*)&h23);
        *(uint2*)(g_hlo + o) = make_uint2(*(uint32_t*)&l01, *(uint32_t*)&l23);
    };
    emit(acc0, lane * 4);
    emit(acc1, 128 + lane * 4);
}

// ---------------- readout: warp per node, h = hhi + hlo (already relu'd) -----
__global__ void k_readout(const float* __restrict__ Wout,
                          const float* __restrict__ bout, float* __restrict__ out) {
    int t = blockIdx.x * blockDim.x + threadIdx.x;
    int node = t >> 5;
    int lane = t & 31;
    if (node >= N_NODES) return;
    const __half* rh = g_hhi + (size_t)node * HID;
    const __half* rl = g_hlo + (size_t)node * HID;
    float acc = 0.0f;
#pragma unroll
    for (int j = lane; j < HID; j += 32)
        acc += (__half2float(rh[j]) + __half2float(rl[j])) * Wout[j];
#pragma unroll
    for (int o = 16; o; o >>= 1) acc += __shfl_xor_sync(0xffffffffu, acc, o);
    if (lane == 0) out[node] = acc + bout[0];
}

extern "C" void kernel_launch(void* const* d_in, const int* in_sizes, int n_in,
                              void* d_out, int out_size) {
    const float* x = (const float*)d_in[0];
    const int* ei = (const int*)d_in[1];
    const float* W0 = (const float*)d_in[2];
    const float* b0 = (const float*)d_in[3];
    const float* W1 = (const float*)d_in[4];
    const float* b1 = (const float*)d_in[5];
    const float* W2 = (const float*)d_in[6];
    const float* b2 = (const float*)d_in[7];
    const float* Wout = (const float*)d_in[8];
    const float* bout = (const float*)d_in[9];
    float* out = (float*)d_out;

    const int SMEM = 2 * STAGE_BYTES;  // 80 KB
    cudaFuncSetAttribute(k_mma<0>, cudaFuncAttributeMaxDynamicSharedMemorySize, SMEM);
    cudaFuncSetAttribute(k_mma<1>, cudaFuncAttributeMaxDynamicSharedMemorySize, SMEM);
    cudaFuncSetAttribute(k_mma<2>, cudaFuncAttributeMaxDynamicSharedMemorySize, SMEM);

    // CSR build + normalization
    k_zero_deg<<<(N_NODES + 255) / 256, 256>>>();
    k_deg_accum<<<(N_EDGES + 255) / 256, 256>>>(ei);
    k_dinv<<<(N_NODES + 255) / 256, 256>>>();
    k_scan1<<<SCAN_BLOCKS, 256>>>();
    k_scan2<<<1, 256>>>();
    k_scan3<<<SCAN_BLOCKS, 256>>>();
    k_fill<<<(N_EDGES + 255) / 256, 256>>>(ei);

    // operand prep
    k_prepx<<<(N_NODES * IN_CH / 4 + 255) / 256, 256>>>(x);
    k_prep<0><<<(IN_CH * HID + 255) / 256, 256>>>(W0);
    k_prep<1><<<(HID * HID + 255) / 256, 256>>>(W1);
    k_prep<2><<<(HID * HID + 255) / 256, 256>>>(W2);

    dim3 grid(HID / 128, (N_NODES + 127) / 128);  // (2, 391)
    const int gatherBlocks = (N_NODES * 32 + 255) / 256;

    // layer 0
    k_mma<0><<<grid, 256, SMEM>>>();
    k_gather<<<gatherBlocks, 256>>>(b0);
    // layer 1
    k_mma<1><<<grid, 256, SMEM>>>();
    k_gather<<<gatherBlocks, 256>>>(b1);
    // layer 2
    k_mma<2><<<grid, 256, SMEM>>>();
    k_gather<<<gatherBlocks, 256>>>(b2);
    // readout
    k_readout<<<(N_NODES * 32 + 255) / 256, 256>>>(Wout, bout, out);
}